// round 8
// baseline (speedup 1.0000x reference)
#include <cuda_runtime.h>

// SetEmbed: out[b] = (sum_{s<n_b} relu(X[b,s]@W1 + b1)) @ W2 + n_b*b2, then @ W3 + b3.
// Persistent kernel (grid=592), 64-row work units, cp.async double-buffered pipeline.
// Per-unit partial pooled16 -> scratch; last-finisher-per-batch does the W2/W3 epilogue
// (atomic counter + threadfence). Hot loop: k-per-lane, register-resident W1, f32x2 FMAs.

#define B_      2048
#define S_      512
#define NFT     64
#define K1      16
#define K2      12
#define NOUT    32
#define UROWS   64                   // rows per work unit
#define CHUNKS  (S_ / UROWS)         // 8 units per batch
#define NU      (B_ * CHUNKS)        // 16384 units
#define RSTRIDE 17                   // float4 per smem row (68 floats)
#define NTHREADS 128
#define GRID    592                  // 148 SMs x 4 CTAs

__device__ float g_scratch[B_ * CHUNKS * K1];  // [b][chunk][k] partial pooled sums
__device__ int   g_cnt[B_];                    // per-batch completion counters (reset by finalizer)

__device__ __forceinline__ unsigned long long pack2(float lo, float hi) {
    unsigned long long r;
    asm("mov.b64 %0, {%1, %2};" : "=l"(r) : "f"(lo), "f"(hi));
    return r;
}
__device__ __forceinline__ void unpack2(unsigned long long v, float& lo, float& hi) {
    asm("mov.b64 {%0, %1}, %2;" : "=f"(lo), "=f"(hi) : "l"(v));
}
// d = a*b + d (two independent fp32 FMAs, one instruction)
__device__ __forceinline__ void ffma2(unsigned long long& d, unsigned long long a,
                                      unsigned long long b) {
    asm("fma.rn.f32x2 %0, %1, %2, %3;" : "=l"(d) : "l"(a), "l"(b), "l"(d));
}
__device__ __forceinline__ unsigned smem_u32(const void* p) {
    return (unsigned)__cvta_generic_to_shared(p);
}

__global__ __launch_bounds__(NTHREADS) void setembed_kernel(
    const float* __restrict__ X, const int* __restrict__ setSizes,
    const float* __restrict__ W1, const float* __restrict__ b1,
    const float* __restrict__ W2, const float* __restrict__ b2,
    const float* __restrict__ W3, const float* __restrict__ b3,
    float* __restrict__ out)
{
    __shared__ __align__(16) float4 buf[2][UROWS * RSTRIDE];  // 2 x 17408 B
    __shared__ int   sizes_s[B_];                             // 8192 B
    __shared__ float red[8][K1 + 1];
    __shared__ float accs_s[K1];
    __shared__ int   flag_s;

    const int t = threadIdx.x;

    // Stage all set sizes once per CTA.
    for (int i = t; i < B_; i += NTHREADS) sizes_s[i] = setSizes[i];

    // W1 column k register-resident as 32 packed feature-pairs.
    const int k    = t & 15;
    const int slot = t >> 4;
    const int warp = t >> 5;
    const int half = (t >> 4) & 1;
    unsigned long long w1r[NFT / 2];
#pragma unroll
    for (int j = 0; j < NFT / 2; j++)
        w1r[j] = pack2(W1[(2 * j) * K1 + k], W1[(2 * j + 1) * K1 + k]);
    const float b1k = b1[k];

    __syncthreads();

    // Unit u covers rows [64c, 64c+cnt) of batch b, b=u>>3, c=u&7.
    // Unit is "active" if it has rows, or if c==0 (chunk0 always runs so every
    // batch gets exactly max(1, ceil(n/64)) contributions -> finalizer fires).
    auto unit_cnt = [&](int u) -> int {
        int b = u >> 3, c = u & 7;
        int n = sizes_s[b];
        int r = n - c * UROWS;
        return r > 0 ? (r < UROWS ? r : UROWS) : 0;
    };
    auto next_active = [&](int u) -> int {
        while (u < NU) {
            if ((u & 7) == 0 || unit_cnt(u) > 0) return u;
            u += GRID;
        }
        return NU;
    };
    auto issue_fetch = [&](int p, int u) {
        const int b = u >> 3, c = u & 7;
        const int cnt = unit_cnt(u);
        const float4* Xg = reinterpret_cast<const float4*>(X)
                           + ((size_t)b * S_ + (size_t)c * UROWS) * 16;
        float4* dst = buf[p];
#pragma unroll
        for (int m = 0; m < 8; m++) {
            int idx = t + m * NTHREADS;        // 0..1023 float4 slots
            int r = idx >> 4, col = idx & 15;
            if (r < cnt) {
                unsigned da = smem_u32(&dst[r * RSTRIDE + col]);
                asm volatile("cp.async.cg.shared.global [%0], [%1], 16;"
                             :: "r"(da), "l"(&Xg[r * 16 + col]));
            }
        }
        asm volatile("cp.async.commit_group;");   // empty group OK for cnt==0
    };

    int u[2];
    u[0] = next_active(blockIdx.x);
    if (u[0] < NU) issue_fetch(0, u[0]);
    u[1] = (u[0] < NU) ? next_active(u[0] + GRID) : NU;
    if (u[1] < NU) issue_fetch(1, u[1]);

    int p = 0;
    while (u[p] < NU) {
        if (u[p ^ 1] < NU) asm volatile("cp.async.wait_group 1;");
        else               asm volatile("cp.async.wait_group 0;");
        __syncthreads();

        const int uu  = u[p];
        const int b   = uu >> 3, c = uu & 7;
        const int cnt = unit_cnt(uu);
        const int n   = sizes_s[b];

        // ---- compute partial pooled16 for this unit ----
        float acc = 0.f;
        const float4* bp = buf[p];
#pragma unroll
        for (int pass = 0; pass < UROWS / 8; pass++) {   // 8 passes, 2 rows/warp
            const int r0 = pass * 8 + warp * 2;          // warp-uniform first row
            if (r0 < cnt) {
                const int r = r0 + half;
                const ulonglong2* xr =
                    reinterpret_cast<const ulonglong2*>(&bp[r * RSTRIDE]);
                unsigned long long h2a = 0ull, h2b = 0ull;
#pragma unroll
                for (int j4 = 0; j4 < 16; j4++) {
                    ulonglong2 q = xr[j4];               // LDS.128: 4 features
                    ffma2(h2a, q.x, w1r[2 * j4]);        // weights from registers
                    ffma2(h2b, q.y, w1r[2 * j4 + 1]);
                }
                float a0, a1, c0, c1;
                unpack2(h2a, a0, a1);
                unpack2(h2b, c0, c1);
                float s = (a0 + a1) + (c0 + c1) + b1k;
                if (r < cnt) acc += fmaxf(s, 0.f);       // relu, tail-masked
            }
        }

        red[slot][k] = acc;
        __syncthreads();
        if (t < K1) {
            float s = 0.f;
#pragma unroll
            for (int ss = 0; ss < 8; ss++) s += red[ss][t];
            g_scratch[(b * CHUNKS + c) * K1 + t] = s;
        }
        __threadfence();              // publish scratch before counter bump
        __syncthreads();

        const int nact = (n > 0) ? ((n + UROWS - 1) >> 6) : 1;
        if (t == 0) {
            int old = atomicAdd(&g_cnt[b], 1);
            flag_s = (old == nact - 1);
            if (flag_s) g_cnt[b] = 0;                    // reset for next replay
        }
        __syncthreads();

        if (flag_s) {                 // last contributor: do batch epilogue
            __threadfence();
            if (t < K1) {
                float s = 0.f;
                for (int cc = 0; cc < nact; cc++)        // fixed order: deterministic
                    s += g_scratch[(b * CHUNKS + cc) * K1 + t];
                accs_s[t] = s;
            }
            __syncthreads();
            if (t < NOUT) {
                const float fn = (float)n;
                float pooled[K2];
#pragma unroll
                for (int j = 0; j < K2; j++) {
                    float pv = fn * b2[j];               // mask-summed b2 term
#pragma unroll
                    for (int kk = 0; kk < K1; kk++) pv += accs_s[kk] * W2[kk * K2 + j];
                    pooled[j] = pv;
                }
                float o = b3[t];
#pragma unroll
                for (int m = 0; m < K2; m++) o += pooled[m] * W3[m * NOUT + t];
                out[(size_t)b * NOUT + t] = o;
            }
            __syncthreads();
        }

        // ---- schedule next unit into the buffer just freed ----
        int un = (u[p ^ 1] < NU) ? next_active(u[p ^ 1] + GRID) : NU;
        u[p] = un;
        if (un < NU) issue_fetch(p, un);
        p ^= 1;
    }
}

extern "C" void kernel_launch(void* const* d_in, const int* in_sizes, int n_in,
                              void* d_out, int out_size)
{
    const float* X  = (const float*)d_in[0];
    const int*   ss = (const int*)  d_in[1];
    const float* W1 = (const float*)d_in[2];
    const float* b1 = (const float*)d_in[3];
    const float* W2 = (const float*)d_in[4];
    const float* b2 = (const float*)d_in[5];
    const float* W3 = (const float*)d_in[6];
    const float* b3 = (const float*)d_in[7];
    float* o = (float*)d_out;
    setembed_kernel<<<GRID, NTHREADS>>>(X, ss, W1, b1, W2, b2, W3, b3, o);
}

// round 11
// speedup vs baseline: 3.3707x; 3.3707x over previous
#include <cuda_runtime.h>

// SetEmbed: out[b] = (sum_{s<n_b} relu(X[b,s]@W1 + b1)) @ W2 + n_b*b2, then @ W3 + b3.
// Tile-parallel main: one CTA per (batch, 128-row tile), cp.async staged, k-per-lane
// with feature-split halves (shfl_xor combine) -> w1r is 32 regs, 6 CTAs/SM.
// Warp-per-batch epilogue kernel finishes W2/W3 from L2-hot scratch.

#define B_      2048
#define S_      512
#define NFT     64
#define K1      16
#define K2      12
#define NOUT    32
#define TSR     128                 // rows per CTA tile
#define NTILES  (S_ / TSR)          // 4
#define RSTRIDE 17                  // float4 per smem row (68 floats)
#define NTHREADS 128

__device__ float g_scratch[B_ * NTILES * K1];   // [b][tile][k] partial pooled sums

__device__ __forceinline__ unsigned long long pack2(float lo, float hi) {
    unsigned long long r;
    asm("mov.b64 %0, {%1, %2};" : "=l"(r) : "f"(lo), "f"(hi));
    return r;
}
__device__ __forceinline__ void unpack2(unsigned long long v, float& lo, float& hi) {
    asm("mov.b64 {%0, %1}, %2;" : "=f"(lo), "=f"(hi) : "l"(v));
}
// d = a*b + d (two independent fp32 FMAs, one instruction)
__device__ __forceinline__ void ffma2(unsigned long long& d, unsigned long long a,
                                      unsigned long long b) {
    asm("fma.rn.f32x2 %0, %1, %2, %3;" : "=l"(d) : "l"(a), "l"(b), "l"(d));
}
__device__ __forceinline__ unsigned smem_u32(const void* p) {
    return (unsigned)__cvta_generic_to_shared(p);
}

__global__ __launch_bounds__(NTHREADS, 6) void setembed_main(
    const float* __restrict__ X, const int* __restrict__ setSizes,
    const float* __restrict__ W1, const float* __restrict__ b1)
{
    __shared__ __align__(16) float4 Xs[TSR * RSTRIDE];   // 34816 B
    __shared__ float red[4][K1];

    const int bid  = blockIdx.x;
    const int b    = bid >> 2;
    const int tile = bid & 3;
    const int t    = threadIdx.x;
    const int n    = setSizes[b];
    const int base = tile * TSR;

    float* myScratch = &g_scratch[(b * NTILES + tile) * K1];
    if (base >= n) {                  // inactive tile: exact zeros
        if (t < K1) myScratch[t] = 0.f;
        return;
    }
    const int cnt = min(TSR, n - base);

    // Stage cnt rows, coalesced float4 cp.async into padded smem rows.
    {
        const float4* Xg = reinterpret_cast<const float4*>(
            X + (size_t)b * S_ * NFT) + (size_t)base * 16;
#pragma unroll
        for (int m = 0; m < 16; m++) {
            int idx = t + m * NTHREADS;       // 0..2047 float4 slots
            int r = idx >> 4, c = idx & 15;
            if (r < cnt) {
                unsigned da = smem_u32(&Xs[r * RSTRIDE + c]);
                asm volatile("cp.async.cg.shared.global [%0], [%1], 16;"
                             :: "r"(da), "l"(&Xg[r * 16 + c]));
            }
        }
        asm volatile("cp.async.commit_group;");
    }

    // Feature-split k-per-lane: lane = fh*16 + k. Each lane owns output k over
    // feature half fh (32 features) -> 16 packed feature-pair weights (32 regs).
    const int lane = t & 31;
    const int warp = t >> 5;
    const int k    = lane & 15;
    const int fh   = lane >> 4;
    unsigned long long w1r[16];
#pragma unroll
    for (int p = 0; p < 16; p++) {
        int f = fh * 32 + 2 * p;
        w1r[p] = pack2(W1[f * K1 + k], W1[(f + 1) * K1 + k]);
    }
    const float b1k = b1[k];

    asm volatile("cp.async.wait_group 0;");
    __syncthreads();

    float acc = 0.f;
#pragma unroll 8
    for (int pass = 0; pass < TSR / 4; pass++) {        // 32 passes, 1 row/warp
        const int r = pass * 4 + warp;                  // interleaved: warp-balanced tails
        if (r < cnt) {                                  // warp-uniform guard
            const ulonglong2* xr =
                reinterpret_cast<const ulonglong2*>(&Xs[r * RSTRIDE]) + fh * 8;
            unsigned long long h2a = 0ull, h2b = 0ull;
#pragma unroll
            for (int j4 = 0; j4 < 8; j4++) {
                ulonglong2 q = xr[j4];                  // LDS.128: 4 features of my half
                ffma2(h2a, q.x, w1r[2 * j4]);           // weights from registers
                ffma2(h2b, q.y, w1r[2 * j4 + 1]);
            }
            float a0, a1, c0, c1;
            unpack2(h2a, a0, a1);
            unpack2(h2b, c0, c1);
            float part = (a0 + a1) + (c0 + c1);         // my half's partial for k
            part += __shfl_xor_sync(0xffffffffu, part, 16);  // combine halves (commutative)
            acc += fmaxf(part + b1k, 0.f);              // relu
        }
    }

    if (fh == 0) red[warp][k] = acc;                    // halves hold identical acc
    __syncthreads();
    if (t < K1)
        myScratch[t] = (red[0][t] + red[1][t]) + (red[2][t] + red[3][t]);
}

__global__ __launch_bounds__(NTHREADS) void setembed_epilogue(
    const int* __restrict__ setSizes,
    const float* __restrict__ W2, const float* __restrict__ b2,
    const float* __restrict__ W3, const float* __restrict__ b3,
    float* __restrict__ out)
{
    const int gw   = (blockIdx.x * NTHREADS + threadIdx.x) >> 5;  // warp = batch
    const int lane = threadIdx.x & 31;
    if (gw >= B_) return;
    const int b = gw;
    const int k = lane & 15;
    const int h = lane >> 4;

    const float* sc = &g_scratch[b * NTILES * K1];
    // accs[k]: chunk order (c_h + c_{h+2}) then xor-combine -> ((c0+c2)+(c1+c3)), deterministic.
    float v = sc[h * K1 + k] + sc[(h + 2) * K1 + k];
    v += __shfl_xor_sync(0xffffffffu, v, 16);           // lane kk (<16) holds accs[kk]

    const float fn = (float)setSizes[b];
    float p = (lane < K2) ? fn * b2[lane] : 0.f;        // mask-summed b2 term
#pragma unroll
    for (int kk = 0; kk < K1; kk++) {
        float a = __shfl_sync(0xffffffffu, v, kk);
        if (lane < K2) p += a * W2[kk * K2 + lane];
    }
    float o = b3[lane];
#pragma unroll
    for (int m = 0; m < K2; m++) {
        float pm = __shfl_sync(0xffffffffu, p, m);
        o += pm * W3[m * NOUT + lane];
    }
    out[(size_t)b * NOUT + lane] = o;
}

extern "C" void kernel_launch(void* const* d_in, const int* in_sizes, int n_in,
                              void* d_out, int out_size)
{
    const float* X  = (const float*)d_in[0];
    const int*   ss = (const int*)  d_in[1];
    const float* W1 = (const float*)d_in[2];
    const float* b1 = (const float*)d_in[3];
    const float* W2 = (const float*)d_in[4];
    const float* b2 = (const float*)d_in[5];
    const float* W3 = (const float*)d_in[6];
    const float* b3 = (const float*)d_in[7];
    float* o = (float*)d_out;
    setembed_main<<<B_ * NTILES, NTHREADS>>>(X, ss, W1, b1);
    setembed_epilogue<<<(B_ * 32 + NTHREADS - 1) / NTHREADS, NTHREADS>>>(
        ss, W2, b2, W3, b3, o);
}

// round 13
// speedup vs baseline: 5.8607x; 1.7387x over previous
#include <cuda_runtime.h>
#include <cstdint>

// SetEmbed: out[b] = (sum_{s<n_b} relu(X[b,s]@W1 + b1)) @ W2 + n_b*b2, then @ W3 + b3.
// Main: one CTA per (batch, 128-row tile). X staged via cp.async into padded smem,
// 64x16 GEMM on the tensor pipe via mma.sync.m16n8k8.tf32 (explicit cvt.rna pre-round),
// relu+pool masked per row AFTER the MMA, partial pooled16 -> scratch.
// Epilogue: warp-per-batch W2/W3 from L2-hot scratch (proven, 5.4us).

#define B_      2048
#define S_      512
#define NFT     64
#define K1      16
#define K2      12
#define NOUT    32
#define TSR     128
#define NTILES  (S_ / TSR)          // 4
#define RST     68                  // floats per smem row (pad: conflict-free frags)
#define NTHREADS 128

__device__ float g_scratch[B_ * NTILES * K1];   // [b][tile][k] partial pooled sums

__device__ __forceinline__ uint32_t f2tf32(float x) {
    uint32_t r;
    asm("cvt.rna.tf32.f32 %0, %1;" : "=r"(r) : "f"(x));
    return r;
}
__device__ __forceinline__ uint32_t smem_u32(const void* p) {
    return (uint32_t)__cvta_generic_to_shared(p);
}
__device__ __forceinline__ void mma16n8k8(float c[4], uint32_t a0, uint32_t a1,
                                          uint32_t a2, uint32_t a3,
                                          uint32_t b0, uint32_t b1) {
    asm volatile(
        "mma.sync.aligned.m16n8k8.row.col.f32.tf32.tf32.f32 "
        "{%0,%1,%2,%3}, {%4,%5,%6,%7}, {%8,%9}, {%0,%1,%2,%3};"
        : "+f"(c[0]), "+f"(c[1]), "+f"(c[2]), "+f"(c[3])
        : "r"(a0), "r"(a1), "r"(a2), "r"(a3), "r"(b0), "r"(b1));
}

__global__ __launch_bounds__(NTHREADS, 6) void setembed_main(
    const float* __restrict__ X, const int* __restrict__ setSizes,
    const float* __restrict__ W1, const float* __restrict__ b1)
{
    __shared__ __align__(16) float Xs[TSR * RST];    // 34816 B
    __shared__ float red[4][K1];

    const int bid  = blockIdx.x;
    const int b    = bid >> 2;
    const int tile = bid & 3;
    const int t    = threadIdx.x;
    const int n    = setSizes[b];
    const int base = tile * TSR;

    float* myScratch = &g_scratch[(b * NTILES + tile) * K1];
    if (base >= n) {                   // inactive tile: exact zeros
        if (t < K1) myScratch[t] = 0.f;
        return;
    }
    const int cnt = min(TSR, n - base);

    // Stage cnt rows, coalesced float4 cp.async. Tail rows stay garbage in smem;
    // their MMA outputs are masked before pooling (rows independent in the GEMM).
    {
        const float4* Xg = reinterpret_cast<const float4*>(
            X + (size_t)b * S_ * NFT) + (size_t)base * 16;
#pragma unroll
        for (int m = 0; m < 16; m++) {
            int idx = t + m * NTHREADS;       // 0..2047 float4 slots
            int r = idx >> 4, c = idx & 15;
            if (r < cnt) {
                unsigned da = smem_u32(&Xs[r * RST + c * 4]);
                asm volatile("cp.async.cg.shared.global [%0], [%1], 16;"
                             :: "r"(da), "l"(&Xg[r * 16 + c]));
            }
        }
        asm volatile("cp.async.commit_group;");
    }

    const int lane = t & 31, warp = t >> 5;
    const int lr = lane & 3;          // col-in-group (k) / C col-pair id
    const int lg = lane >> 2;         // row-in-group (m) / B n id

    // B fragments (W1^T as tf32), register-resident; LDG overlaps cp.async.
    uint32_t bf[8][2][2];             // [kt][nt][b0/b1]
#pragma unroll
    for (int kt = 0; kt < 8; kt++)
#pragma unroll
        for (int nt = 0; nt < 2; nt++) {
            bf[kt][nt][0] = f2tf32(W1[(kt * 8 + lr)     * K1 + nt * 8 + lg]);
            bf[kt][nt][1] = f2tf32(W1[(kt * 8 + lr + 4) * K1 + nt * 8 + lg]);
        }
    // bias for this thread's 4 pooled columns {2lr, 2lr+1, 8+2lr, 8+2lr+1}
    float b1c[4];
    b1c[0] = b1[2 * lr];     b1c[1] = b1[2 * lr + 1];
    b1c[2] = b1[8 + 2 * lr]; b1c[3] = b1[8 + 2 * lr + 1];

    asm volatile("cp.async.wait_group 0;");
    __syncthreads();

    float accp[4] = {0.f, 0.f, 0.f, 0.f};

#pragma unroll
    for (int i = 0; i < 2; i++) {                 // 2 m-tiles per warp
        const int r0b = (2 * warp + i) * 16;      // warp-uniform mtile base row
        if (r0b < cnt) {
            float c0[4] = {0.f, 0.f, 0.f, 0.f};   // nt=0 accum
            float c1[4] = {0.f, 0.f, 0.f, 0.f};   // nt=1 accum
#pragma unroll
            for (int kt = 0; kt < 8; kt++) {
                const float* xp = &Xs[(r0b + lg) * RST + kt * 8 + lr];
                uint32_t a0 = f2tf32(xp[0]);            // (row lg,   col lr)
                uint32_t a1 = f2tf32(xp[8 * RST]);      // (row lg+8, col lr)
                uint32_t a2 = f2tf32(xp[4]);            // (row lg,   col lr+4)
                uint32_t a3 = f2tf32(xp[8 * RST + 4]);  // (row lg+8, col lr+4)
                mma16n8k8(c0, a0, a1, a2, a3, bf[kt][0][0], bf[kt][0][1]);
                mma16n8k8(c1, a0, a1, a2, a3, bf[kt][1][0], bf[kt][1][1]);
            }
            const int r0 = r0b + lg, r1 = r0 + 8;
            if (r0 < cnt) {                        // relu + pool, row-masked
                accp[0] += fmaxf(c0[0] + b1c[0], 0.f);
                accp[1] += fmaxf(c0[1] + b1c[1], 0.f);
                accp[2] += fmaxf(c1[0] + b1c[2], 0.f);
                accp[3] += fmaxf(c1[1] + b1c[3], 0.f);
            }
            if (r1 < cnt) {
                accp[0] += fmaxf(c0[2] + b1c[0], 0.f);
                accp[1] += fmaxf(c0[3] + b1c[1], 0.f);
                accp[2] += fmaxf(c1[2] + b1c[2], 0.f);
                accp[3] += fmaxf(c1[3] + b1c[3], 0.f);
            }
        }
    }

    // Reduce over the 8 row-groups (lanes sharing lr): xor 16,8,4. Deterministic.
#pragma unroll
    for (int j = 0; j < 4; j++) {
        accp[j] += __shfl_xor_sync(0xffffffffu, accp[j], 16);
        accp[j] += __shfl_xor_sync(0xffffffffu, accp[j], 8);
        accp[j] += __shfl_xor_sync(0xffffffffu, accp[j], 4);
    }
    if (lg == 0) {                                 // lanes 0..3 cover all 16 cols
        red[warp][2 * lr]         = accp[0];
        red[warp][2 * lr + 1]     = accp[1];
        red[warp][8 + 2 * lr]     = accp[2];
        red[warp][8 + 2 * lr + 1] = accp[3];
    }
    __syncthreads();
    if (t < K1)
        myScratch[t] = (red[0][t] + red[1][t]) + (red[2][t] + red[3][t]);
}

__global__ __launch_bounds__(NTHREADS) void setembed_epilogue(
    const int* __restrict__ setSizes,
    const float* __restrict__ W2, const float* __restrict__ b2,
    const float* __restrict__ W3, const float* __restrict__ b3,
    float* __restrict__ out)
{
    const int gw   = (blockIdx.x * NTHREADS + threadIdx.x) >> 5;  // warp = batch
    const int lane = threadIdx.x & 31;
    if (gw >= B_) return;
    const int b = gw;
    const int k = lane & 15;
    const int h = lane >> 4;

    const float* sc = &g_scratch[b * NTILES * K1];
    float v = sc[h * K1 + k] + sc[(h + 2) * K1 + k];
    v += __shfl_xor_sync(0xffffffffu, v, 16);     // lane kk (<16) holds accs[kk]

    const float fn = (float)setSizes[b];
    float p = (lane < K2) ? fn * b2[lane] : 0.f;  // mask-summed b2 term
#pragma unroll
    for (int kk = 0; kk < K1; kk++) {
        float a = __shfl_sync(0xffffffffu, v, kk);
        if (lane < K2) p += a * W2[kk * K2 + lane];
    }
    float o = b3[lane];
#pragma unroll
    for (int m = 0; m < K2; m++) {
        float pm = __shfl_sync(0xffffffffu, p, m);
        o += pm * W3[m * NOUT + lane];
    }
    out[(size_t)b * NOUT + lane] = o;
}

extern "C" void kernel_launch(void* const* d_in, const int* in_sizes, int n_in,
                              void* d_out, int out_size)
{
    const float* X  = (const float*)d_in[0];
    const int*   ss = (const int*)  d_in[1];
    const float* W1 = (const float*)d_in[2];
    const float* b1 = (const float*)d_in[3];
    const float* W2 = (const float*)d_in[4];
    const float* b2 = (const float*)d_in[5];
    const float* W3 = (const float*)d_in[6];
    const float* b3 = (const float*)d_in[7];
    float* o = (float*)d_out;
    setembed_main<<<B_ * NTILES, NTHREADS>>>(X, ss, W1, b1);
    setembed_epilogue<<<(B_ * 32 + NTHREADS - 1) / NTHREADS, NTHREADS>>>(
        ss, W2, b2, W3, b3, o);
}